// round 12
// baseline (speedup 1.0000x reference)
#include <cuda_runtime.h>
#include <cuda_bf16.h>
#include <math.h>

#define NN   100000
#define BB   32
#define NPER 3125
#define EE   200000
#define NTOT 100032
#define ETOT 500032
#define EBLK ((ETOT + 255) / 256)
#define N2B  64
#define N2G  ((NN + N2B - 1) / N2B)

typedef unsigned long long ull;

// ---------------- scratch ----------------
__device__ float d_M[64 * 128];
__device__ float d_c[128];
__device__ ull   d_W2p[64 * 64];     // packed (W2[2k][c], W2[2k+1][c]) pairs
__device__ float d_xh1[NTOT * 128];
__device__ float d_s1[NTOT * 2];
__device__ float d_d1[NTOT * 2];
__device__ float d_den1[NTOT * 2];
__device__ float d_acc1[NTOT * 128];
__device__ float d_s2[NTOT];
__device__ float d_d2[NTOT];
__device__ float d_den2[NTOT];
__device__ float d_acc2[BB * 64];

// ---------------- helpers ----------------
__device__ __forceinline__ float lrelu(float x) { return x > 0.f ? x : 0.2f * x; }

__device__ __forceinline__ void edge_sd(int e, const int* __restrict__ ei, int& s, int& d) {
    if (e < EE)               { s = ei[e]; d = ei[EE + e]; }
    else if (e < EE + NN)     { int i = e - EE;          d = i; s = NN + i / NPER; }
    else if (e < EE + 2 * NN) { int i = e - EE - NN;     s = i; d = NN + i / NPER; }
    else                      { int i = e - EE - 2 * NN; s = i; d = i; }
}

__device__ __forceinline__ ull f2pk(float lo, float hi) {
    ull r;
    asm("mov.b64 %0, {%1, %2};" : "=l"(r) : "f"(lo), "f"(hi));
    return r;
}
__device__ __forceinline__ void f2fma(ull& d, ull a, ull b) {
    asm("fma.rn.f32x2 %0, %1, %2, %0;" : "+l"(d) : "l"(a), "l"(b));
}
__device__ __forceinline__ float2 f2up(ull v) {
    float2 r;
    asm("mov.b64 {%0, %1}, %2;" : "=f"(r.x), "=f"(r.y) : "l"(v));
    return r;
}
__device__ __forceinline__ float f2sum(ull v) {
    float2 r = f2up(v);
    return r.x + r.y;
}

// ---------------- pre: M (per-block local T), c, glb inits, src/dst emit, W2 packing ----------------
__global__ __launch_bounds__(256) void k_pre(const float* __restrict__ ltW, const float* __restrict__ ltb,
                                             const float* __restrict__ lvW, const float* __restrict__ lvb,
                                             const float* __restrict__ glbW, const float* __restrict__ glbb,
                                             const float* __restrict__ glbNode, const float* __restrict__ gat1_W,
                                             const float* __restrict__ a1s, const float* __restrict__ a1d,
                                             const int* __restrict__ ei, const float* __restrict__ W2,
                                             float* __restrict__ out) {
    int b = blockIdx.x, tid = threadIdx.x;
    if (b < 32) {
        __shared__ float sT[2 * 64];
        if (tid < 128) {
            int r = tid >> 6, m = tid & 63;
            int i = 2 * b + r;
            float a = 0.f;
            if (i < 39) {
                for (int k = 0; k < 64; k++) a += ltW[i * 64 + k] * glbW[(64 + k) * 64 + m];
            } else {
                int iv = i - 39;
                for (int k = 0; k < 64; k++) a += lvW[iv * 64 + k] * glbW[k * 64 + m];
            }
            sT[r * 64 + m] = a;
        }
        __syncthreads();
        int r = tid >> 7, j = tid & 127;
        float a = 0.f;
        #pragma unroll 8
        for (int k = 0; k < 64; k++) a += sT[r * 64 + k] * gat1_W[k * 128 + j];
        d_M[(2 * b + r) * 128 + j] = a;
    } else if (b == 32) {
        __shared__ float sbx[64];
        __shared__ float sxg[128];
        __shared__ float sc4[4];
        __shared__ float sex[2];
        if (tid < 64) {
            float a = glbb[tid];
            for (int k = 0; k < 64; k++)
                a += lvb[k] * glbW[k * 64 + tid] + ltb[k] * glbW[(64 + k) * 64 + tid];
            sbx[tid] = a;
        }
        __syncthreads();
        if (tid < 128) {
            float xg = 0.f, cj = 0.f;
            for (int m = 0; m < 64; m++) {
                float w = gat1_W[m * 128 + tid];
                xg += glbNode[m] * w;
                cj += sbx[m] * w;
            }
            sxg[tid] = xg;
            d_c[tid] = cj;
        }
        __syncthreads();
        if (tid == 0) {
            float s0 = 0, s1 = 0, dd0 = 0, dd1 = 0;
            for (int c = 0; c < 64; c++) {
                s0 += sxg[c] * a1s[c];           dd0 += sxg[c] * a1d[c];
                s1 += sxg[64 + c] * a1s[64 + c]; dd1 += sxg[64 + c] * a1d[64 + c];
            }
            sc4[0] = s0; sc4[1] = s1; sc4[2] = dd0; sc4[3] = dd1;
            sex[0] = expf(lrelu(s0 + dd0));
            sex[1] = expf(lrelu(s1 + dd1));
        }
        __syncthreads();
        if (tid < 128) {
            int h = tid >> 6;
            float xg = sxg[tid];
            float ai = sex[h] * xg;
            for (int g = 0; g < BB; g++) {
                d_xh1[(NN + g) * 128 + tid] = xg;
                d_acc1[(NN + g) * 128 + tid] = ai;
            }
        }
        if (tid < 64) d_den1[NN * 2 + tid] = sex[tid & 1];
        if (tid < BB) d_den2[NN + tid] = 0.f;
        for (int t = tid; t < BB * 64; t += 256) d_acc2[t] = 0.f;
        if (tid < BB) {
            d_s1[(NN + tid) * 2]     = sc4[0];
            d_s1[(NN + tid) * 2 + 1] = sc4[1];
            d_d1[(NN + tid) * 2]     = sc4[2];
            d_d1[(NN + tid) * 2 + 1] = sc4[3];
        }
    } else if (b < 33 + EBLK) {
        int e = (b - 33) * 256 + tid;
        if (e < ETOT) {
            int s, d; edge_sd(e, ei, s, d);
            out[2048 + e] = (float)s;
            out[2048 + ETOT + e] = (float)d;
        }
    } else {
        int idx = (b - 33 - EBLK) * 256 + tid;
        if (idx < 64 * 64) {
            int k2 = idx >> 6, c = idx & 63;
            d_W2p[idx] = f2pk(W2[(2 * k2) * 64 + c], W2[(2 * k2 + 1) * 64 + c]);
        }
    }
}

// ---------------- fused LN + GEMM + det-edge init + glb partials ----------------
__global__ __launch_bounds__(256) void k_node1(const float* __restrict__ tf,
                                               const float* __restrict__ g_t, const float* __restrict__ b_t,
                                               const float* __restrict__ g_v, const float* __restrict__ b_v,
                                               const float* __restrict__ a1s, const float* __restrict__ a1d)
{
    __shared__ __align__(16) ull sMt[32 * 128];
    __shared__ __align__(16) ull snp[32][32];
    __shared__ float sc[128], sas[128], sad[128], sxg[128];
    __shared__ float sgp[64], sbp[64];
    __shared__ float sgs[2], sgd[2];
    __shared__ float sacc[2][128];
    __shared__ float sden[2][2];
    int tid = threadIdx.x;
    for (int t = tid; t < 32 * 128; t += 256) {
        int i2 = t >> 7, j = t & 127;
        sMt[t] = f2pk(d_M[(2 * i2) * 128 + j], d_M[(2 * i2 + 1) * 128 + j]);
    }
    if (tid < 128) {
        sc[tid] = d_c[tid]; sas[tid] = a1s[tid]; sad[tid] = a1d[tid];
        sxg[tid] = d_xh1[NN * 128 + tid];
    }
    if (tid < 64) {
        sgp[tid] = (tid < 39) ? g_t[tid] : g_v[tid - 39];
        sbp[tid] = (tid < 39) ? b_t[tid] : b_v[tid - 39];
    }
    if (tid < 2) { sgs[tid] = d_s1[NN * 2 + tid]; sgd[tid] = d_d1[NN * 2 + tid]; }
    sacc[tid >> 7][tid & 127] = 0.f;
    if (tid < 4) sden[tid >> 1][tid & 1] = 0.f;
    __syncthreads();
    int w = tid >> 5, lane = tid & 31;
    int vb = blockIdx.x * 32 + w * 4;
    int p0 = lane * 2, p1 = lane * 2 + 1;

    #pragma unroll
    for (int q = 0; q < 4; q++) {
        int v = vb + q;
        float2 p = ((const float2*)tf)[v * 32 + lane];
        float st = 0, sst = 0, sv = 0, ssv = 0;
        if (p0 < 39) { st += p.x; sst += p.x * p.x; } else { sv += p.x; ssv += p.x * p.x; }
        if (p1 < 39) { st += p.y; sst += p.y * p.y; } else { sv += p.y; ssv += p.y * p.y; }
        #pragma unroll
        for (int o = 16; o; o >>= 1) {
            st  += __shfl_xor_sync(0xffffffffu, st, o);
            sst += __shfl_xor_sync(0xffffffffu, sst, o);
            sv  += __shfl_xor_sync(0xffffffffu, sv, o);
            ssv += __shfl_xor_sync(0xffffffffu, ssv, o);
        }
        float mt = st * (1.f / 39.f), vt = sst * (1.f / 39.f) - mt * mt;
        float mv = sv * (1.f / 25.f), vv = ssv * (1.f / 25.f) - mv * mv;
        float rt = rsqrtf(vt + 1e-5f), rv = rsqrtf(vv + 1e-5f);
        float n0 = (p0 < 39) ? (p.x - mt) * rt : (p.x - mv) * rv;
        float n1 = (p1 < 39) ? (p.y - mt) * rt : (p.y - mv) * rv;
        n0 = n0 * sgp[p0] + sbp[p0];
        n1 = n1 * sgp[p1] + sbp[p1];
        snp[w * 4 + q][lane] = f2pk(n0, n1);
    }
    __syncwarp();

    int j0 = lane * 4;
    ull acc[4][4];
    #pragma unroll
    for (int q = 0; q < 4; q++)
        #pragma unroll
        for (int c = 0; c < 4; c++) acc[q][c] = 0ull;
    #pragma unroll 2
    for (int i2 = 0; i2 < 32; i2 += 2) {
        ulonglong2 mA0 = *(const ulonglong2*)&sMt[i2 * 128 + j0];
        ulonglong2 mB0 = *(const ulonglong2*)&sMt[i2 * 128 + j0 + 2];
        ulonglong2 mA1 = *(const ulonglong2*)&sMt[(i2 + 1) * 128 + j0];
        ulonglong2 mB1 = *(const ulonglong2*)&sMt[(i2 + 1) * 128 + j0 + 2];
        #pragma unroll
        for (int q = 0; q < 4; q++) {
            ulonglong2 xq = *(const ulonglong2*)&snp[w * 4 + q][i2];
            f2fma(acc[q][0], xq.x, mA0.x);
            f2fma(acc[q][1], xq.x, mA0.y);
            f2fma(acc[q][2], xq.x, mB0.x);
            f2fma(acc[q][3], xq.x, mB0.y);
            f2fma(acc[q][0], xq.y, mA1.x);
            f2fma(acc[q][1], xq.y, mA1.y);
            f2fma(acc[q][2], xq.y, mB1.x);
            f2fma(acc[q][3], xq.y, mB1.y);
        }
    }

    float4 as4 = *(const float4*)&sas[j0];
    float4 ad4 = *(const float4*)&sad[j0];
    float4 xg4 = *(const float4*)&sxg[j0];
    float4 c4  = *(const float4*)&sc[j0];
    int h = lane >> 4;
    float s1g = sgs[h], d1g = sgd[h];
    int g0blk = (blockIdx.x * 32) / NPER;
    bool fast = (vb / NPER) == ((vb + 3) / NPER);
    float4 pac = make_float4(0.f, 0.f, 0.f, 0.f);
    float pden = 0.f;
    #pragma unroll
    for (int q = 0; q < 4; q++) {
        int v = vb + q;
        float4 a;
        a.x = f2sum(acc[q][0]) + c4.x;
        a.y = f2sum(acc[q][1]) + c4.y;
        a.z = f2sum(acc[q][2]) + c4.z;
        a.w = f2sum(acc[q][3]) + c4.w;
        *(float4*)&d_xh1[v * 128 + j0] = a;
        float ps = a.x * as4.x + a.y * as4.y + a.z * as4.z + a.w * as4.w;
        float pd = a.x * ad4.x + a.y * ad4.y + a.z * ad4.z + a.w * ad4.w;
        #pragma unroll
        for (int o = 8; o; o >>= 1) {
            ps += __shfl_xor_sync(0xffffffffu, ps, o);
            pd += __shfl_xor_sync(0xffffffffu, pd, o);
        }
        float exg = expf(lrelu(s1g + pd));
        float exs = expf(lrelu(ps + pd));
        float4 ai;
        ai.x = exg * xg4.x + exs * a.x;
        ai.y = exg * xg4.y + exs * a.y;
        ai.z = exg * xg4.z + exs * a.z;
        ai.w = exg * xg4.w + exs * a.w;
        *(float4*)&d_acc1[v * 128 + j0] = ai;
        if (lane == 0)  { d_s1[v * 2]     = ps; d_d1[v * 2]     = pd; d_den1[v * 2]     = exg + exs; }
        if (lane == 16) { d_s1[v * 2 + 1] = ps; d_d1[v * 2 + 1] = pd; d_den1[v * 2 + 1] = exg + exs; }
        float exv = expf(lrelu(ps + d1g));
        if (fast) {
            pac.x += exv * a.x; pac.y += exv * a.y;
            pac.z += exv * a.z; pac.w += exv * a.w;
            pden += exv;
        } else {
            int sel = (v / NPER) != g0blk;
            atomicAdd(&sacc[sel][j0 + 0], exv * a.x);
            atomicAdd(&sacc[sel][j0 + 1], exv * a.y);
            atomicAdd(&sacc[sel][j0 + 2], exv * a.z);
            atomicAdd(&sacc[sel][j0 + 3], exv * a.w);
            if (lane == 0 || lane == 16) atomicAdd(&sden[sel][h], exv);
        }
    }
    if (fast) {
        int sel = (vb / NPER) != g0blk;
        atomicAdd(&sacc[sel][j0 + 0], pac.x);
        atomicAdd(&sacc[sel][j0 + 1], pac.y);
        atomicAdd(&sacc[sel][j0 + 2], pac.z);
        atomicAdd(&sacc[sel][j0 + 3], pac.w);
        if (lane == 0 || lane == 16) atomicAdd(&sden[sel][h], pden);
    }
    __syncthreads();
    int gl = (blockIdx.x * 32 + 31) / NPER;
    if (tid < 128) {
        atomicAdd(&d_acc1[(NN + g0blk) * 128 + tid], sacc[0][tid]);
    } else if (gl != g0blk) {
        atomicAdd(&d_acc1[(NN + gl) * 128 + (tid - 128)], sacc[1][tid - 128]);
    }
    if (tid < 2) atomicAdd(&d_den1[(NN + g0blk) * 2 + tid], sden[0][tid]);
    if (gl != g0blk && (tid == 2 || tid == 3)) atomicAdd(&d_den1[(NN + gl) * 2 + (tid - 2)], sden[1][tid - 2]);
}

// ---------------- GAT1 random edges: 4 edges per warp ----------------
__global__ __launch_bounds__(256) void k_e2acc(const int* __restrict__ ei) {
    int wp = (blockIdx.x * 256 + threadIdx.x) >> 5;
    int e0 = wp * 4;
    if (e0 >= EE) return;
    int lane = threadIdx.x & 31;
    int j = lane * 4;
    int s[4], d[4];
    #pragma unroll
    for (int i = 0; i < 4; i++) { s[i] = __ldg(&ei[e0 + i]); d[i] = __ldg(&ei[EE + e0 + i]); }
    float4 x[4];
    #pragma unroll
    for (int i = 0; i < 4; i++) x[i] = *(const float4*)&d_xh1[s[i] * 128 + j];
    float2 sv[4], dv[4];
    #pragma unroll
    for (int i = 0; i < 4; i++) {
        sv[i] = *(const float2*)&d_s1[s[i] * 2];
        dv[i] = *(const float2*)&d_d1[d[i] * 2];
    }
    float ex0[4], ex1[4];
    #pragma unroll
    for (int i = 0; i < 4; i++) {
        ex0[i] = expf(lrelu(sv[i].x + dv[i].x));
        ex1[i] = expf(lrelu(sv[i].y + dv[i].y));
    }
    int li = lane >> 3;
    if ((lane & 7) == 0)
        asm volatile("red.global.add.v2.f32 [%0], {%1,%2};"
                     :: "l"(&d_den1[d[li] * 2]), "f"(ex0[li]), "f"(ex1[li]) : "memory");
    #pragma unroll
    for (int i = 0; i < 4; i++) {
        float wg = (j < 64) ? ex0[i] : ex1[i];
        asm volatile("red.global.add.v4.f32 [%0], {%1,%2,%3,%4};"
                     :: "l"(&d_acc1[d[i] * 128 + j]),
                        "f"(wg * x[i].x), "f"(wg * x[i].y), "f"(wg * x[i].z), "f"(wg * x[i].w)
                     : "memory");
    }
}

// ---------------- finish GAT1 + GAT2 projection (two half-passes of 4 nodes) + glb ----------------
__global__ __launch_bounds__(256, 4) void k_node2(const float* __restrict__ b1,
                                                  const float* __restrict__ a2s, const float* __restrict__ a2d)
{
    __shared__ __align__(16) ull shp[N2B][64];   // 32KB
    __shared__ float sacc2[2][64];
    __shared__ float sden2[2];
    __shared__ __align__(8) float hg[2][128];
    __shared__ float ogp[4][2][64];
    __shared__ float sg2[2][2];
    int tid = threadIdx.x;
    int vb0 = blockIdx.x * N2B;
    int g0blk = vb0 / NPER;
    int vlast = vb0 + N2B - 1; if (vlast >= NN) vlast = NN - 1;
    int gl = vlast / NPER;
    if (tid < 128) sacc2[tid >> 6][tid & 63] = 0.f;
    if (tid < 2) sden2[tid] = 0.f;
    if (tid < 4) sg2[tid >> 1][tid & 1] = 0.f;
    {
        int e = tid >> 7, k = tid & 127;
        int g = e ? gl : g0blk;
        float den = d_den1[(NN + g) * 2 + (k >= 64)];
        hg[e][k] = fmaxf(d_acc1[(NN + g) * 128 + k] / (den + 1e-16f) + b1[k], 0.f);
    }
    __syncthreads();
    {
        int c = tid & 63, r = tid >> 6;
        ull pA = 0ull, pB = 0ull;
        #pragma unroll 4
        for (int k2 = r * 16; k2 < r * 16 + 16; k2++) {
            ull mw = __ldg(&d_W2p[k2 * 64 + c]);
            float2 h0 = *(const float2*)&hg[0][2 * k2];
            float2 h1 = *(const float2*)&hg[1][2 * k2];
            f2fma(pA, f2pk(h0.x, h0.y), mw);
            f2fma(pB, f2pk(h1.x, h1.y), mw);
        }
        ogp[r][0][c] = f2sum(pA);
        ogp[r][1][c] = f2sum(pB);
    }
    __syncthreads();
    if (tid < 128) {
        int e = tid >> 6, c = tid & 63;
        float o = ogp[0][e][c] + ogp[1][e][c] + ogp[2][e][c] + ogp[3][e][c];
        ogp[0][e][c] = o;
        float pps = o * a2s[c], ppd = o * a2d[c];
        #pragma unroll
        for (int of = 16; of; of >>= 1) {
            pps += __shfl_xor_sync(0xffffffffu, pps, of);
            ppd += __shfl_xor_sync(0xffffffffu, ppd, of);
        }
        if ((tid & 31) == 0) {
            atomicAdd(&sg2[e][0], pps);
            atomicAdd(&sg2[e][1], ppd);
        }
    }
    __syncthreads();
    float s2g0 = sg2[0][0], d2g0 = sg2[0][1];
    float s2gl = sg2[1][0], d2gl = sg2[1][1];
    {
        bool desig0 = (g0blk * NPER == vb0);
        bool desigl = (gl != g0blk);
        if (tid < 128) {
            int e = tid >> 6, c = tid & 63;
            bool desig = e ? desigl : desig0;
            if (desig) {
                int g = e ? gl : g0blk;
                float s2g = e ? s2gl : s2g0;
                float d2g = e ? d2gl : d2g0;
                float exs = expf(lrelu(s2g + d2g));
                atomicAdd(&d_acc2[g * 64 + c], exs * ogp[0][e][c]);
                if (c == 0) {
                    atomicAdd(&d_den2[NN + g], exs);
                    d_s2[NN + g] = s2g;
                    d_d2[NN + g] = d2g;
                }
            }
        }
    }

    int w = tid >> 5, lane = tid & 31;
    int vb = vb0 + w * 8;
    int j0 = lane * 4;
    int h = (j0 >= 64);
    float4 b14 = *(const float4*)&b1[j0];

    #pragma unroll
    for (int q = 0; q < 8; q++) {
        int v = vb + q;
        float2 den2r = *(const float2*)&d_den1[v * 2];
        float r = 1.f / ((h ? den2r.y : den2r.x) + 1e-16f);
        float4 num = *(const float4*)&d_acc1[v * 128 + j0];
        float h0 = fmaxf(num.x * r + b14.x, 0.f);
        float h1 = fmaxf(num.y * r + b14.y, 0.f);
        float h2 = fmaxf(num.z * r + b14.z, 0.f);
        float h3 = fmaxf(num.w * r + b14.w, 0.f);
        shp[w * 8 + q][j0 / 2]     = f2pk(h0, h1);
        shp[w * 8 + q][j0 / 2 + 1] = f2pk(h2, h3);
    }
    __syncwarp();

    int c0 = lane * 2;
    float2 as2 = *(const float2*)&a2s[c0];
    float2 ad2 = *(const float2*)&a2d[c0];
    bool fast = (vb + 7 < NN) && ((vb / NPER) == ((vb + 7) / NPER));
    float2 pac = make_float2(0.f, 0.f);
    float pden = 0.f;

    #pragma unroll 1
    for (int half = 0; half < 2; half++) {
        int qb = half * 4;
        ull accq[4][2];
        #pragma unroll
        for (int q = 0; q < 4; q++) { accq[q][0] = 0ull; accq[q][1] = 0ull; }
        #pragma unroll 2
        for (int k2 = 0; k2 < 64; k2 += 2) {
            ulonglong2 mw0 = __ldg((const ulonglong2*)&d_W2p[k2 * 64 + c0]);
            ulonglong2 mw1 = __ldg((const ulonglong2*)&d_W2p[(k2 + 1) * 64 + c0]);
            #pragma unroll
            for (int q = 0; q < 4; q++) {
                ulonglong2 xp = *(const ulonglong2*)&shp[w * 8 + qb + q][k2];
                f2fma(accq[q][0], xp.x, mw0.x);
                f2fma(accq[q][1], xp.x, mw0.y);
                f2fma(accq[q][0], xp.y, mw1.x);
                f2fma(accq[q][1], xp.y, mw1.y);
            }
        }
        #pragma unroll
        for (int q = 0; q < 4; q++) {
            int v = vb + qb + q;
            float2 o;
            o.x = f2sum(accq[q][0]);
            o.y = f2sum(accq[q][1]);
            float ps = o.x * as2.x + o.y * as2.y;
            float pd = o.x * ad2.x + o.y * ad2.y;
            #pragma unroll
            for (int of = 16; of; of >>= 1) {
                ps += __shfl_xor_sync(0xffffffffu, ps, of);
                pd += __shfl_xor_sync(0xffffffffu, pd, of);
            }
            if (fast) {
                int sel = (v / NPER) != g0blk;
                float s2g = sel ? s2gl : s2g0;
                float d2g = sel ? d2gl : d2g0;
                if (lane == 0) {
                    d_s2[v] = ps; d_d2[v] = pd;
                    d_den2[v] = expf(lrelu(s2g + pd)) + expf(lrelu(ps + pd));
                }
                float exv = expf(lrelu(ps + d2g));
                pac.x += exv * o.x; pac.y += exv * o.y;
                pden += exv;
            } else if (v < NN) {
                int sel = (v / NPER) != g0blk;
                float s2g = sel ? s2gl : s2g0;
                float d2g = sel ? d2gl : d2g0;
                if (lane == 0) {
                    d_s2[v] = ps; d_d2[v] = pd;
                    d_den2[v] = expf(lrelu(s2g + pd)) + expf(lrelu(ps + pd));
                }
                float exv = expf(lrelu(ps + d2g));
                atomicAdd(&sacc2[sel][c0],     exv * o.x);
                atomicAdd(&sacc2[sel][c0 + 1], exv * o.y);
                if (lane == 0) atomicAdd(&sden2[sel], exv);
            }
        }
    }
    if (fast) {
        int sel = (vb / NPER) != g0blk;
        atomicAdd(&sacc2[sel][c0],     pac.x);
        atomicAdd(&sacc2[sel][c0 + 1], pac.y);
        if (lane == 0) atomicAdd(&sden2[sel], pden);
    }
    __syncthreads();
    if (tid < 64) {
        atomicAdd(&d_acc2[g0blk * 64 + tid], sacc2[0][tid]);
    } else if (tid < 128 && gl != g0blk) {
        atomicAdd(&d_acc2[gl * 64 + (tid - 64)], sacc2[1][tid - 64]);
    }
    if (tid == 0) atomicAdd(&d_den2[NN + g0blk], sden2[0]);
    if (tid == 1 && gl != g0blk) atomicAdd(&d_den2[NN + gl], sden2[1]);
}

// ---------------- GAT2 den: random edges only ----------------
__global__ void k_post2r(const int* __restrict__ ei) {
    int e = blockIdx.x * blockDim.x + threadIdx.x;
    if (e >= EE) return;
    int s = ei[e], d = ei[EE + e];
    atomicAdd(&d_den2[d], expf(lrelu(d_s2[s] + d_d2[d])));
}

// ---------------- att + tree_glb ----------------
__global__ void k_attfin(const int* __restrict__ ei, const float* __restrict__ b2,
                         float* __restrict__ out) {
    int b = blockIdx.x;
    if (b < EBLK) {
        int e = b * 256 + threadIdx.x;
        if (e >= ETOT) return;
        int s, d; edge_sd(e, ei, s, d);
        float ex = expf(lrelu(d_s2[s] + d_d2[d]));
        out[2048 + 2 * ETOT + e] = ex / (d_den2[d] + 1e-16f);
    } else {
        int t = (b - EBLK) * 256 + threadIdx.x;
        int g = t >> 6, j = t & 63;
        out[t] = d_acc2[t] / (d_den2[NN + g] + 1e-16f) + b2[j];
    }
}

// ---------------- launch ----------------
extern "C" void kernel_launch(void* const* d_in, const int* in_sizes, int n_in,
                              void* d_out, int out_size) {
    const float* tree_feature = (const float*)d_in[0];
    const int*   edge_index   = (const int*)d_in[1];
    const float* ln_tree_g  = (const float*)d_in[4];
    const float* ln_tree_b  = (const float*)d_in[5];
    const float* lin_tree_W = (const float*)d_in[6];
    const float* lin_tree_b = (const float*)d_in[7];
    const float* ln_var_g   = (const float*)d_in[8];
    const float* ln_var_b   = (const float*)d_in[9];
    const float* lin_var_W  = (const float*)d_in[10];
    const float* lin_var_b  = (const float*)d_in[11];
    const float* glb_W      = (const float*)d_in[12];
    const float* glb_b      = (const float*)d_in[13];
    const float* glbNode    = (const float*)d_in[14];
    const float* gat1_W     = (const float*)d_in[15];
    const float* gat1_as    = (const float*)d_in[16];
    const float* gat1_ad    = (const float*)d_in[17];
    const float* gat1_b     = (const float*)d_in[18];
    const float* gat2_W     = (const float*)d_in[19];
    const float* gat2_as    = (const float*)d_in[20];
    const float* gat2_ad    = (const float*)d_in[21];
    const float* gat2_b     = (const float*)d_in[22];
    float* out = (float*)d_out;

    k_pre<<<33 + EBLK + 16, 256>>>(lin_tree_W, lin_tree_b, lin_var_W, lin_var_b, glb_W, glb_b,
                                   glbNode, gat1_W, gat1_as, gat1_ad, edge_index, gat2_W, out);
    k_node1<<<NN / 32, 256>>>(tree_feature, ln_tree_g, ln_tree_b,
                              ln_var_g, ln_var_b, gat1_as, gat1_ad);
    k_e2acc<<<(EE / 4 * 32) / 256, 256>>>(edge_index);
    k_node2<<<N2G, 256>>>(gat1_b, gat2_as, gat2_ad);
    k_post2r<<<(EE + 255) / 256, 256>>>(edge_index);
    k_attfin<<<EBLK + 8, 256>>>(edge_index, gat2_b, out);
}

// round 13
// speedup vs baseline: 1.0715x; 1.0715x over previous
#include <cuda_runtime.h>
#include <cuda_bf16.h>
#include <math.h>

#define NN   100000
#define BB   32
#define NPER 3125
#define EE   200000
#define NTOT 100032
#define ETOT 500032
#define EBLK ((ETOT + 255) / 256)
#define N2B  64
#define N2G  ((NN + N2B - 1) / N2B)

typedef unsigned long long ull;

// ---------------- scratch ----------------
__device__ ull   d_Mp[32 * 128];     // packed (M[2i][j], M[2i+1][j]) pairs
__device__ float d_c[128];
__device__ ull   d_W2p[64 * 64];     // packed (W2[2k][c], W2[2k+1][c]) pairs
__device__ float d_xh1[NTOT * 128];
__device__ float d_s1[NTOT * 2];
__device__ float d_d1[NTOT * 2];
__device__ float d_den1[NTOT * 2];
__device__ float d_acc1[NTOT * 128];
__device__ float d_s2[NTOT];
__device__ float d_d2[NTOT];
__device__ float d_den2[NTOT];
__device__ float d_acc2[BB * 64];

// ---------------- helpers ----------------
__device__ __forceinline__ float lrelu(float x) { return x > 0.f ? x : 0.2f * x; }

__device__ __forceinline__ void edge_sd(int e, const int* __restrict__ ei, int& s, int& d) {
    if (e < EE)               { s = ei[e]; d = ei[EE + e]; }
    else if (e < EE + NN)     { int i = e - EE;          d = i; s = NN + i / NPER; }
    else if (e < EE + 2 * NN) { int i = e - EE - NN;     s = i; d = NN + i / NPER; }
    else                      { int i = e - EE - 2 * NN; s = i; d = i; }
}

__device__ __forceinline__ ull f2pk(float lo, float hi) {
    ull r;
    asm("mov.b64 %0, {%1, %2};" : "=l"(r) : "f"(lo), "f"(hi));
    return r;
}
__device__ __forceinline__ void f2fma(ull& d, ull a, ull b) {
    asm("fma.rn.f32x2 %0, %1, %2, %0;" : "+l"(d) : "l"(a), "l"(b));
}
__device__ __forceinline__ float2 f2up(ull v) {
    float2 r;
    asm("mov.b64 {%0, %1}, %2;" : "=f"(r.x), "=f"(r.y) : "l"(v));
    return r;
}
__device__ __forceinline__ float f2sum(ull v) {
    float2 r = f2up(v);
    return r.x + r.y;
}

// ---------------- pre: Mp (packed), c, glb inits, src/dst emit, W2 packing ----------------
__global__ __launch_bounds__(256) void k_pre(const float* __restrict__ ltW, const float* __restrict__ ltb,
                                             const float* __restrict__ lvW, const float* __restrict__ lvb,
                                             const float* __restrict__ glbW, const float* __restrict__ glbb,
                                             const float* __restrict__ glbNode, const float* __restrict__ gat1_W,
                                             const float* __restrict__ a1s, const float* __restrict__ a1d,
                                             const int* __restrict__ ei, const float* __restrict__ W2,
                                             float* __restrict__ out) {
    int b = blockIdx.x, tid = threadIdx.x;
    if (b < 32) {
        __shared__ float sT[2 * 64];
        __shared__ float sM2[2][128];
        if (tid < 128) {
            int r = tid >> 6, m = tid & 63;
            int i = 2 * b + r;
            float a = 0.f;
            if (i < 39) {
                for (int k = 0; k < 64; k++) a += ltW[i * 64 + k] * glbW[(64 + k) * 64 + m];
            } else {
                int iv = i - 39;
                for (int k = 0; k < 64; k++) a += lvW[iv * 64 + k] * glbW[k * 64 + m];
            }
            sT[r * 64 + m] = a;
        }
        __syncthreads();
        int r = tid >> 7, j = tid & 127;
        float a = 0.f;
        #pragma unroll 8
        for (int k = 0; k < 64; k++) a += sT[r * 64 + k] * gat1_W[k * 128 + j];
        sM2[r][j] = a;
        __syncthreads();
        if (tid < 128) d_Mp[b * 128 + tid] = f2pk(sM2[0][tid], sM2[1][tid]);
    } else if (b == 32) {
        __shared__ float sbx[64];
        __shared__ float sxg[128];
        __shared__ float sc4[4];
        __shared__ float sex[2];
        if (tid < 64) {
            float a = glbb[tid];
            for (int k = 0; k < 64; k++)
                a += lvb[k] * glbW[k * 64 + tid] + ltb[k] * glbW[(64 + k) * 64 + tid];
            sbx[tid] = a;
        }
        __syncthreads();
        if (tid < 128) {
            float xg = 0.f, cj = 0.f;
            for (int m = 0; m < 64; m++) {
                float w = gat1_W[m * 128 + tid];
                xg += glbNode[m] * w;
                cj += sbx[m] * w;
            }
            sxg[tid] = xg;
            d_c[tid] = cj;
        }
        __syncthreads();
        if (tid == 0) {
            float s0 = 0, s1 = 0, dd0 = 0, dd1 = 0;
            for (int c = 0; c < 64; c++) {
                s0 += sxg[c] * a1s[c];           dd0 += sxg[c] * a1d[c];
                s1 += sxg[64 + c] * a1s[64 + c]; dd1 += sxg[64 + c] * a1d[64 + c];
            }
            sc4[0] = s0; sc4[1] = s1; sc4[2] = dd0; sc4[3] = dd1;
            sex[0] = expf(lrelu(s0 + dd0));
            sex[1] = expf(lrelu(s1 + dd1));
        }
        __syncthreads();
        if (tid < 128) {
            int h = tid >> 6;
            float xg = sxg[tid];
            float ai = sex[h] * xg;
            for (int g = 0; g < BB; g++) {
                d_xh1[(NN + g) * 128 + tid] = xg;
                d_acc1[(NN + g) * 128 + tid] = ai;
            }
        }
        if (tid < 64) d_den1[NN * 2 + tid] = sex[tid & 1];
        if (tid < BB) d_den2[NN + tid] = 0.f;
        for (int t = tid; t < BB * 64; t += 256) d_acc2[t] = 0.f;
        if (tid < BB) {
            d_s1[(NN + tid) * 2]     = sc4[0];
            d_s1[(NN + tid) * 2 + 1] = sc4[1];
            d_d1[(NN + tid) * 2]     = sc4[2];
            d_d1[(NN + tid) * 2 + 1] = sc4[3];
        }
    } else if (b < 33 + EBLK) {
        int e = (b - 33) * 256 + tid;
        if (e < ETOT) {
            int s, d; edge_sd(e, ei, s, d);
            out[2048 + e] = (float)s;
            out[2048 + ETOT + e] = (float)d;
        }
    } else {
        int idx = (b - 33 - EBLK) * 256 + tid;
        if (idx < 64 * 64) {
            int k2 = idx >> 6, c = idx & 63;
            d_W2p[idx] = f2pk(W2[(2 * k2) * 64 + c], W2[(2 * k2 + 1) * 64 + c]);
        }
    }
}

// ---------------- fused LN + GEMM (LDG weights) + det-edge init + glb partials ----------------
__global__ __launch_bounds__(256) void k_node1(const float* __restrict__ tf,
                                               const float* __restrict__ g_t, const float* __restrict__ b_t,
                                               const float* __restrict__ g_v, const float* __restrict__ b_v,
                                               const float* __restrict__ a1s, const float* __restrict__ a1d)
{
    __shared__ __align__(16) ull snp[32][32];
    __shared__ float sc[128], sas[128], sad[128], sxg[128];
    __shared__ float sgp[64], sbp[64];
    __shared__ float sgs[2], sgd[2];
    __shared__ float sacc[2][128];
    __shared__ float sden[2][2];
    int tid = threadIdx.x;
    if (tid < 128) {
        sc[tid] = d_c[tid]; sas[tid] = a1s[tid]; sad[tid] = a1d[tid];
        sxg[tid] = d_xh1[NN * 128 + tid];
    }
    if (tid < 64) {
        sgp[tid] = (tid < 39) ? g_t[tid] : g_v[tid - 39];
        sbp[tid] = (tid < 39) ? b_t[tid] : b_v[tid - 39];
    }
    if (tid < 2) { sgs[tid] = d_s1[NN * 2 + tid]; sgd[tid] = d_d1[NN * 2 + tid]; }
    sacc[tid >> 7][tid & 127] = 0.f;
    if (tid < 4) sden[tid >> 1][tid & 1] = 0.f;
    __syncthreads();
    int w = tid >> 5, lane = tid & 31;
    int vb = blockIdx.x * 32 + w * 4;
    int p0 = lane * 2, p1 = lane * 2 + 1;

    #pragma unroll
    for (int q = 0; q < 4; q++) {
        int v = vb + q;
        float2 p = ((const float2*)tf)[v * 32 + lane];
        float st = 0, sst = 0, sv = 0, ssv = 0;
        if (p0 < 39) { st += p.x; sst += p.x * p.x; } else { sv += p.x; ssv += p.x * p.x; }
        if (p1 < 39) { st += p.y; sst += p.y * p.y; } else { sv += p.y; ssv += p.y * p.y; }
        #pragma unroll
        for (int o = 16; o; o >>= 1) {
            st  += __shfl_xor_sync(0xffffffffu, st, o);
            sst += __shfl_xor_sync(0xffffffffu, sst, o);
            sv  += __shfl_xor_sync(0xffffffffu, sv, o);
            ssv += __shfl_xor_sync(0xffffffffu, ssv, o);
        }
        float mt = st * (1.f / 39.f), vt = sst * (1.f / 39.f) - mt * mt;
        float mv = sv * (1.f / 25.f), vv = ssv * (1.f / 25.f) - mv * mv;
        float rt = rsqrtf(vt + 1e-5f), rv = rsqrtf(vv + 1e-5f);
        float n0 = (p0 < 39) ? (p.x - mt) * rt : (p.x - mv) * rv;
        float n1 = (p1 < 39) ? (p.y - mt) * rt : (p.y - mv) * rv;
        n0 = n0 * sgp[p0] + sbp[p0];
        n1 = n1 * sgp[p1] + sbp[p1];
        snp[w * 4 + q][lane] = f2pk(n0, n1);
    }
    __syncwarp();

    int j0 = lane * 4;
    ull acc[4][4];
    #pragma unroll
    for (int q = 0; q < 4; q++)
        #pragma unroll
        for (int c = 0; c < 4; c++) acc[q][c] = 0ull;
    #pragma unroll 2
    for (int i2 = 0; i2 < 32; i2 += 2) {
        ulonglong2 mA0 = __ldg((const ulonglong2*)&d_Mp[i2 * 128 + j0]);
        ulonglong2 mB0 = __ldg((const ulonglong2*)&d_Mp[i2 * 128 + j0 + 2]);
        ulonglong2 mA1 = __ldg((const ulonglong2*)&d_Mp[(i2 + 1) * 128 + j0]);
        ulonglong2 mB1 = __ldg((const ulonglong2*)&d_Mp[(i2 + 1) * 128 + j0 + 2]);
        #pragma unroll
        for (int q = 0; q < 4; q++) {
            ulonglong2 xq = *(const ulonglong2*)&snp[w * 4 + q][i2];
            f2fma(acc[q][0], xq.x, mA0.x);
            f2fma(acc[q][1], xq.x, mA0.y);
            f2fma(acc[q][2], xq.x, mB0.x);
            f2fma(acc[q][3], xq.x, mB0.y);
            f2fma(acc[q][0], xq.y, mA1.x);
            f2fma(acc[q][1], xq.y, mA1.y);
            f2fma(acc[q][2], xq.y, mB1.x);
            f2fma(acc[q][3], xq.y, mB1.y);
        }
    }

    float4 as4 = *(const float4*)&sas[j0];
    float4 ad4 = *(const float4*)&sad[j0];
    float4 xg4 = *(const float4*)&sxg[j0];
    float4 c4  = *(const float4*)&sc[j0];
    int h = lane >> 4;
    float s1g = sgs[h], d1g = sgd[h];
    int g0blk = (blockIdx.x * 32) / NPER;
    bool fast = (vb / NPER) == ((vb + 3) / NPER);
    float4 pac = make_float4(0.f, 0.f, 0.f, 0.f);
    float pden = 0.f;
    #pragma unroll
    for (int q = 0; q < 4; q++) {
        int v = vb + q;
        float4 a;
        a.x = f2sum(acc[q][0]) + c4.x;
        a.y = f2sum(acc[q][1]) + c4.y;
        a.z = f2sum(acc[q][2]) + c4.z;
        a.w = f2sum(acc[q][3]) + c4.w;
        *(float4*)&d_xh1[v * 128 + j0] = a;
        float ps = a.x * as4.x + a.y * as4.y + a.z * as4.z + a.w * as4.w;
        float pd = a.x * ad4.x + a.y * ad4.y + a.z * ad4.z + a.w * ad4.w;
        #pragma unroll
        for (int o = 8; o; o >>= 1) {
            ps += __shfl_xor_sync(0xffffffffu, ps, o);
            pd += __shfl_xor_sync(0xffffffffu, pd, o);
        }
        float exg = expf(lrelu(s1g + pd));
        float exs = expf(lrelu(ps + pd));
        float4 ai;
        ai.x = exg * xg4.x + exs * a.x;
        ai.y = exg * xg4.y + exs * a.y;
        ai.z = exg * xg4.z + exs * a.z;
        ai.w = exg * xg4.w + exs * a.w;
        *(float4*)&d_acc1[v * 128 + j0] = ai;
        if (lane == 0)  { d_s1[v * 2]     = ps; d_d1[v * 2]     = pd; d_den1[v * 2]     = exg + exs; }
        if (lane == 16) { d_s1[v * 2 + 1] = ps; d_d1[v * 2 + 1] = pd; d_den1[v * 2 + 1] = exg + exs; }
        float exv = expf(lrelu(ps + d1g));
        if (fast) {
            pac.x += exv * a.x; pac.y += exv * a.y;
            pac.z += exv * a.z; pac.w += exv * a.w;
            pden += exv;
        } else {
            int sel = (v / NPER) != g0blk;
            atomicAdd(&sacc[sel][j0 + 0], exv * a.x);
            atomicAdd(&sacc[sel][j0 + 1], exv * a.y);
            atomicAdd(&sacc[sel][j0 + 2], exv * a.z);
            atomicAdd(&sacc[sel][j0 + 3], exv * a.w);
            if (lane == 0 || lane == 16) atomicAdd(&sden[sel][h], exv);
        }
    }
    if (fast) {
        int sel = (vb / NPER) != g0blk;
        atomicAdd(&sacc[sel][j0 + 0], pac.x);
        atomicAdd(&sacc[sel][j0 + 1], pac.y);
        atomicAdd(&sacc[sel][j0 + 2], pac.z);
        atomicAdd(&sacc[sel][j0 + 3], pac.w);
        if (lane == 0 || lane == 16) atomicAdd(&sden[sel][h], pden);
    }
    __syncthreads();
    int gl = (blockIdx.x * 32 + 31) / NPER;
    if (tid < 128) {
        atomicAdd(&d_acc1[(NN + g0blk) * 128 + tid], sacc[0][tid]);
    } else if (gl != g0blk) {
        atomicAdd(&d_acc1[(NN + gl) * 128 + (tid - 128)], sacc[1][tid - 128]);
    }
    if (tid < 2) atomicAdd(&d_den1[(NN + g0blk) * 2 + tid], sden[0][tid]);
    if (gl != g0blk && (tid == 2 || tid == 3)) atomicAdd(&d_den1[(NN + gl) * 2 + (tid - 2)], sden[1][tid - 2]);
}

// ---------------- GAT1 random edges: 4 edges per warp ----------------
__global__ __launch_bounds__(256) void k_e2acc(const int* __restrict__ ei) {
    int wp = (blockIdx.x * 256 + threadIdx.x) >> 5;
    int e0 = wp * 4;
    if (e0 >= EE) return;
    int lane = threadIdx.x & 31;
    int j = lane * 4;
    int s[4], d[4];
    #pragma unroll
    for (int i = 0; i < 4; i++) { s[i] = __ldg(&ei[e0 + i]); d[i] = __ldg(&ei[EE + e0 + i]); }
    float4 x[4];
    #pragma unroll
    for (int i = 0; i < 4; i++) x[i] = *(const float4*)&d_xh1[s[i] * 128 + j];
    float2 sv[4], dv[4];
    #pragma unroll
    for (int i = 0; i < 4; i++) {
        sv[i] = *(const float2*)&d_s1[s[i] * 2];
        dv[i] = *(const float2*)&d_d1[d[i] * 2];
    }
    float ex0[4], ex1[4];
    #pragma unroll
    for (int i = 0; i < 4; i++) {
        ex0[i] = expf(lrelu(sv[i].x + dv[i].x));
        ex1[i] = expf(lrelu(sv[i].y + dv[i].y));
    }
    int li = lane >> 3;
    if ((lane & 7) == 0)
        asm volatile("red.global.add.v2.f32 [%0], {%1,%2};"
                     :: "l"(&d_den1[d[li] * 2]), "f"(ex0[li]), "f"(ex1[li]) : "memory");
    #pragma unroll
    for (int i = 0; i < 4; i++) {
        float wg = (j < 64) ? ex0[i] : ex1[i];
        asm volatile("red.global.add.v4.f32 [%0], {%1,%2,%3,%4};"
                     :: "l"(&d_acc1[d[i] * 128 + j]),
                        "f"(wg * x[i].x), "f"(wg * x[i].y), "f"(wg * x[i].z), "f"(wg * x[i].w)
                     : "memory");
    }
}

// ---------------- finish GAT1 + GAT2 projection (8 nodes/warp, LDG weights) + glb ----------------
__global__ __launch_bounds__(256, 3) void k_node2(const float* __restrict__ b1,
                                                  const float* __restrict__ a2s, const float* __restrict__ a2d)
{
    __shared__ __align__(16) ull shp[N2B][64];   // 32KB
    __shared__ float sacc2[2][64];
    __shared__ float sden2[2];
    __shared__ __align__(8) float hg[2][128];
    __shared__ float ogp[4][2][64];
    __shared__ float sg2[2][2];
    int tid = threadIdx.x;
    int vb0 = blockIdx.x * N2B;
    int g0blk = vb0 / NPER;
    int vlast = vb0 + N2B - 1; if (vlast >= NN) vlast = NN - 1;
    int gl = vlast / NPER;
    if (tid < 128) sacc2[tid >> 6][tid & 63] = 0.f;
    if (tid < 2) sden2[tid] = 0.f;
    if (tid < 4) sg2[tid >> 1][tid & 1] = 0.f;
    {
        int e = tid >> 7, k = tid & 127;
        int g = e ? gl : g0blk;
        float den = d_den1[(NN + g) * 2 + (k >= 64)];
        hg[e][k] = fmaxf(d_acc1[(NN + g) * 128 + k] / (den + 1e-16f) + b1[k], 0.f);
    }
    __syncthreads();
    {
        int c = tid & 63, r = tid >> 6;
        ull pA = 0ull, pB = 0ull;
        #pragma unroll 4
        for (int k2 = r * 16; k2 < r * 16 + 16; k2++) {
            ull mw = __ldg(&d_W2p[k2 * 64 + c]);
            float2 h0 = *(const float2*)&hg[0][2 * k2];
            float2 h1 = *(const float2*)&hg[1][2 * k2];
            f2fma(pA, f2pk(h0.x, h0.y), mw);
            f2fma(pB, f2pk(h1.x, h1.y), mw);
        }
        ogp[r][0][c] = f2sum(pA);
        ogp[r][1][c] = f2sum(pB);
    }
    __syncthreads();
    if (tid < 128) {
        int e = tid >> 6, c = tid & 63;
        float o = ogp[0][e][c] + ogp[1][e][c] + ogp[2][e][c] + ogp[3][e][c];
        ogp[0][e][c] = o;
        float pps = o * a2s[c], ppd = o * a2d[c];
        #pragma unroll
        for (int of = 16; of; of >>= 1) {
            pps += __shfl_xor_sync(0xffffffffu, pps, of);
            ppd += __shfl_xor_sync(0xffffffffu, ppd, of);
        }
        if ((tid & 31) == 0) {
            atomicAdd(&sg2[e][0], pps);
            atomicAdd(&sg2[e][1], ppd);
        }
    }
    __syncthreads();
    float s2g0 = sg2[0][0], d2g0 = sg2[0][1];
    float s2gl = sg2[1][0], d2gl = sg2[1][1];
    {
        bool desig0 = (g0blk * NPER == vb0);
        bool desigl = (gl != g0blk);
        if (tid < 128) {
            int e = tid >> 6, c = tid & 63;
            bool desig = e ? desigl : desig0;
            if (desig) {
                int g = e ? gl : g0blk;
                float s2g = e ? s2gl : s2g0;
                float d2g = e ? d2gl : d2g0;
                float exs = expf(lrelu(s2g + d2g));
                atomicAdd(&d_acc2[g * 64 + c], exs * ogp[0][e][c]);
                if (c == 0) {
                    atomicAdd(&d_den2[NN + g], exs);
                    d_s2[NN + g] = s2g;
                    d_d2[NN + g] = d2g;
                }
            }
        }
    }

    int w = tid >> 5, lane = tid & 31;
    int vb = vb0 + w * 8;
    int j0 = lane * 4;
    int h = (j0 >= 64);
    float4 b14 = *(const float4*)&b1[j0];

    #pragma unroll
    for (int q = 0; q < 8; q++) {
        int v = vb + q;
        float2 den2r = *(const float2*)&d_den1[v * 2];
        float r = 1.f / ((h ? den2r.y : den2r.x) + 1e-16f);
        float4 num = *(const float4*)&d_acc1[v * 128 + j0];
        float h0 = fmaxf(num.x * r + b14.x, 0.f);
        float h1 = fmaxf(num.y * r + b14.y, 0.f);
        float h2 = fmaxf(num.z * r + b14.z, 0.f);
        float h3 = fmaxf(num.w * r + b14.w, 0.f);
        shp[w * 8 + q][j0 / 2]     = f2pk(h0, h1);
        shp[w * 8 + q][j0 / 2 + 1] = f2pk(h2, h3);
    }
    __syncwarp();

    int c0 = lane * 2;
    ull accq[8][2];
    #pragma unroll
    for (int q = 0; q < 8; q++) { accq[q][0] = 0ull; accq[q][1] = 0ull; }
    #pragma unroll 2
    for (int k2 = 0; k2 < 64; k2 += 2) {
        ulonglong2 mw0 = __ldg((const ulonglong2*)&d_W2p[k2 * 64 + c0]);
        ulonglong2 mw1 = __ldg((const ulonglong2*)&d_W2p[(k2 + 1) * 64 + c0]);
        #pragma unroll
        for (int q = 0; q < 8; q++) {
            ulonglong2 xp = *(const ulonglong2*)&shp[w * 8 + q][k2];
            f2fma(accq[q][0], xp.x, mw0.x);
            f2fma(accq[q][1], xp.x, mw0.y);
            f2fma(accq[q][0], xp.y, mw1.x);
            f2fma(accq[q][1], xp.y, mw1.y);
        }
    }

    float2 as2 = *(const float2*)&a2s[c0];
    float2 ad2 = *(const float2*)&a2d[c0];
    bool fast = (vb + 7 < NN) && ((vb / NPER) == ((vb + 7) / NPER));
    float2 pac = make_float2(0.f, 0.f);
    float pden = 0.f;
    #pragma unroll
    for (int q = 0; q < 8; q++) {
        int v = vb + q;
        float2 o;
        o.x = f2sum(accq[q][0]);
        o.y = f2sum(accq[q][1]);
        float ps = o.x * as2.x + o.y * as2.y;
        float pd = o.x * ad2.x + o.y * ad2.y;
        #pragma unroll
        for (int of = 16; of; of >>= 1) {
            ps += __shfl_xor_sync(0xffffffffu, ps, of);
            pd += __shfl_xor_sync(0xffffffffu, pd, of);
        }
        if (fast) {
            int sel = (v / NPER) != g0blk;
            float s2g = sel ? s2gl : s2g0;
            float d2g = sel ? d2gl : d2g0;
            if (lane == 0) {
                d_s2[v] = ps; d_d2[v] = pd;
                d_den2[v] = expf(lrelu(s2g + pd)) + expf(lrelu(ps + pd));
            }
            float exv = expf(lrelu(ps + d2g));
            pac.x += exv * o.x; pac.y += exv * o.y;
            pden += exv;
        } else if (v < NN) {
            int sel = (v / NPER) != g0blk;
            float s2g = sel ? s2gl : s2g0;
            float d2g = sel ? d2gl : d2g0;
            if (lane == 0) {
                d_s2[v] = ps; d_d2[v] = pd;
                d_den2[v] = expf(lrelu(s2g + pd)) + expf(lrelu(ps + pd));
            }
            float exv = expf(lrelu(ps + d2g));
            atomicAdd(&sacc2[sel][c0],     exv * o.x);
            atomicAdd(&sacc2[sel][c0 + 1], exv * o.y);
            if (lane == 0) atomicAdd(&sden2[sel], exv);
        }
    }
    if (fast) {
        int sel = (vb / NPER) != g0blk;
        atomicAdd(&sacc2[sel][c0],     pac.x);
        atomicAdd(&sacc2[sel][c0 + 1], pac.y);
        if (lane == 0) atomicAdd(&sden2[sel], pden);
    }
    __syncthreads();
    if (tid < 64) {
        atomicAdd(&d_acc2[g0blk * 64 + tid], sacc2[0][tid]);
    } else if (tid < 128 && gl != g0blk) {
        atomicAdd(&d_acc2[gl * 64 + (tid - 64)], sacc2[1][tid - 64]);
    }
    if (tid == 0) atomicAdd(&d_den2[NN + g0blk], sden2[0]);
    if (tid == 1 && gl != g0blk) atomicAdd(&d_den2[NN + gl], sden2[1]);
}

// ---------------- GAT2 den: random edges only ----------------
__global__ void k_post2r(const int* __restrict__ ei) {
    int e = blockIdx.x * blockDim.x + threadIdx.x;
    if (e >= EE) return;
    int s = ei[e], d = ei[EE + e];
    atomicAdd(&d_den2[d], expf(lrelu(d_s2[s] + d_d2[d])));
}

// ---------------- att + tree_glb ----------------
__global__ void k_attfin(const int* __restrict__ ei, const float* __restrict__ b2,
                         float* __restrict__ out) {
    int b = blockIdx.x;
    if (b < EBLK) {
        int e = b * 256 + threadIdx.x;
        if (e >= ETOT) return;
        int s, d; edge_sd(e, ei, s, d);
        float ex = expf(lrelu(d_s2[s] + d_d2[d]));
        out[2048 + 2 * ETOT + e] = ex / (d_den2[d] + 1e-16f);
    } else {
        int t = (b - EBLK) * 256 + threadIdx.x;
        int g = t >> 6, j = t & 63;
        out[t] = d_acc2[t] / (d_den2[NN + g] + 1e-16f) + b2[j];
    }
}

// ---------------- launch ----------------
extern "C" void kernel_launch(void* const* d_in, const int* in_sizes, int n_in,
                              void* d_out, int out_size) {
    const float* tree_feature = (const float*)d_in[0];
    const int*   edge_index   = (const int*)d_in[1];
    const float* ln_tree_g  = (const float*)d_in[4];
    const float* ln_tree_b  = (const float*)d_in[5];
    const float* lin_tree_W = (const float*)d_in[6];
    const float* lin_tree_b = (const float*)d_in[7];
    const float* ln_var_g   = (const float*)d_in[8];
    const float* ln_var_b   = (const float*)d_in[9];
    const float* lin_var_W  = (const float*)d_in[10];
    const float* lin_var_b  = (const float*)d_in[11];
    const float* glb_W      = (const float*)d_in[12];
    const float* glb_b      = (const float*)d_in[13];
    const float* glbNode    = (const float*)d_in[14];
    const float* gat1_W     = (const float*)d_in[15];
    const float* gat1_as    = (const float*)d_in[16];
    const float* gat1_ad    = (const float*)d_in[17];
    const float* gat1_b     = (const float*)d_in[18];
    const float* gat2_W     = (const float*)d_in[19];
    const float* gat2_as    = (const float*)d_in[20];
    const float* gat2_ad    = (const float*)d_in[21];
    const float* gat2_b     = (const float*)d_in[22];
    float* out = (float*)d_out;

    k_pre<<<33 + EBLK + 16, 256>>>(lin_tree_W, lin_tree_b, lin_var_W, lin_var_b, glb_W, glb_b,
                                   glbNode, gat1_W, gat1_as, gat1_ad, edge_index, gat2_W, out);
    k_node1<<<NN / 32, 256>>>(tree_feature, ln_tree_g, ln_tree_b,
                              ln_var_g, ln_var_b, gat1_as, gat1_ad);
    k_e2acc<<<(EE / 4 * 32) / 256, 256>>>(edge_index);
    k_node2<<<N2G, 256>>>(gat1_b, gat2_as, gat2_ad);
    k_post2r<<<(EE + 255) / 256, 256>>>(edge_index);
    k_attfin<<<EBLK + 8, 256>>>(edge_index, gat2_b, out);
}